// round 11
// baseline (speedup 1.0000x reference)
#include <cuda_runtime.h>
#include <cstdint>

// Problem constants: N=100000, E=3200000, DIN=128, H=256, M=500, O=100
#define NN  100000
#define EE  3200000
#define DIN 128
#define HH  256
#define MM  500
#define MP  512
#define OO  100

#define SCAN_B 1024
#define NBLK ((NN + SCAN_B - 1) / SCAN_B)   // 98

// ---- scratch (static device globals; referenced ONLY from device code) ----
__device__ int   g_deg[NN];
__device__ int   g_off[NN];
__device__ int   g_cur[NN];
__device__ int   g_bsum[128];
__device__ int   g_src[EE];
__device__ float g_dinv[NN];
__device__ __align__(16) float g_xagg[NN * DIN];   // 51.2 MB
__device__ __align__(16) float g_h   [NN * HH];    // 102.4 MB
__device__ __align__(16) float g_hagg[NN * HH];    // 102.4 MB
__device__ __align__(16) float g_p   [NN * MP];    // 204.8 MB

// ============================ helpers ============================
__device__ __forceinline__ void fma2(unsigned long long& d, unsigned long long a, unsigned long long b) {
    asm("fma.rn.f32x2 %0, %1, %2, %0;" : "+l"(d) : "l"(a), "l"(b));
}
__device__ __forceinline__ void unpack2(unsigned long long v, float& lo, float& hi) {
    uint32_t l, h;
    asm("mov.b64 {%0, %1}, %2;" : "=r"(l), "=r"(h) : "l"(v));
    lo = __uint_as_float(l); hi = __uint_as_float(h);
}
__device__ __forceinline__ float softplus_f(float z) {
    float e = __expf(-fabsf(z));
    return fmaxf(z, 0.f) + __logf(1.f + e);
}
__device__ __forceinline__ float tanh_f(float x) {
    float e = __expf(-2.f * x);
    return (1.f - e) / (1.f + e);
}

// ============================ graph preprocessing ============================
__global__ void k_zero_deg() {
    int i = blockIdx.x * blockDim.x + threadIdx.x;
    if (i < NN) g_deg[i] = 0;
}
__global__ void k_count(const int* __restrict__ ei) {
    int e = blockIdx.x * blockDim.x + threadIdx.x;
    if (e < EE) { int d = ei[EE + e]; if ((unsigned)d < NN) atomicAdd(&g_deg[d], 1); }
}
__global__ void k_dinv() {
    int i = blockIdx.x * blockDim.x + threadIdx.x;
    if (i < NN) g_dinv[i] = rsqrtf((float)g_deg[i] + 2.0f);
}
__global__ void k_scan1() {
    __shared__ int sm[SCAN_B];
    int t = threadIdx.x, i = blockIdx.x * SCAN_B + t;
    int v = (i < NN) ? g_deg[i] : 0;
    sm[t] = v; __syncthreads();
    for (int s = 1; s < SCAN_B; s <<= 1) {
        int add = (t >= s) ? sm[t - s] : 0;
        __syncthreads(); sm[t] += add; __syncthreads();
    }
    if (i < NN) g_off[i] = sm[t] - v;
    if (t == SCAN_B - 1) g_bsum[blockIdx.x] = sm[t];
}
__global__ void k_scan2() {
    __shared__ int sm[128];
    int t = threadIdx.x;
    int v = (t < NBLK) ? g_bsum[t] : 0;
    sm[t] = v; __syncthreads();
    for (int s = 1; s < 128; s <<= 1) {
        int add = (t >= s) ? sm[t - s] : 0;
        __syncthreads(); sm[t] += add; __syncthreads();
    }
    if (t < NBLK) g_bsum[t] = sm[t] - v;
}
__global__ void k_scan3() {
    int i = blockIdx.x * blockDim.x + threadIdx.x;
    if (i < NN) { int o = g_off[i] + g_bsum[i / SCAN_B]; g_off[i] = o; g_cur[i] = o; }
}
__global__ void k_fill(const int* __restrict__ ei) {
    int e = blockIdx.x * blockDim.x + threadIdx.x;
    if (e < EE) {
        int s = ei[e], d = ei[EE + e];
        if ((unsigned)s < NN && (unsigned)d < NN) g_src[atomicAdd(&g_cur[d], 1)] = s;
    }
}

// ---------------- CSR gather (warp per dst node, 128 channels, 4-edge unroll) ----------------
template<int LAYER>
__global__ void k_gather(const float* __restrict__ Xin, int coff) {
    constexpr int C = (LAYER == 0) ? DIN : HH;
    const float* X = (LAYER == 0) ? Xin : (const float*)g_h;
    float* OUT = (LAYER == 0) ? g_xagg : g_hagg;
    int w = (blockIdx.x * blockDim.x + threadIdx.x) >> 5;
    int lane = threadIdx.x & 31;
    if (w >= NN) return;
    float dv = g_dinv[w];
    const float* Xc = X + coff + lane * 4;
    float4 acc;
    {
        float4 v = *(const float4*)(Xc + (long)w * C);
        float sc = 2.0f * dv * dv;
        acc.x = v.x * sc; acc.y = v.y * sc; acc.z = v.z * sc; acc.w = v.w * sc;
    }
    int off = g_off[w], dg = g_deg[w];
    int j = 0;
    for (; j + 4 <= dg; j += 4) {
        int s0 = g_src[off + j], s1 = g_src[off + j + 1];
        int s2 = g_src[off + j + 2], s3 = g_src[off + j + 3];
        float c0 = g_dinv[s0] * dv, c1 = g_dinv[s1] * dv;
        float c2 = g_dinv[s2] * dv, c3 = g_dinv[s3] * dv;
        float4 v0 = *(const float4*)(Xc + (long)s0 * C);
        float4 v1 = *(const float4*)(Xc + (long)s1 * C);
        float4 v2 = *(const float4*)(Xc + (long)s2 * C);
        float4 v3 = *(const float4*)(Xc + (long)s3 * C);
        acc.x += v0.x * c0 + v1.x * c1 + v2.x * c2 + v3.x * c3;
        acc.y += v0.y * c0 + v1.y * c1 + v2.y * c2 + v3.y * c3;
        acc.z += v0.z * c0 + v1.z * c1 + v2.z * c2 + v3.z * c3;
        acc.w += v0.w * c0 + v1.w * c1 + v2.w * c2 + v3.w * c3;
    }
    for (; j < dg; j++) {
        int s0 = g_src[off + j];
        float c0 = g_dinv[s0] * dv;
        float4 v0 = *(const float4*)(Xc + (long)s0 * C);
        acc.x += v0.x * c0; acc.y += v0.y * c0; acc.z += v0.z * c0; acc.w += v0.w * c0;
    }
    *(float4*)(OUT + coff + (long)w * C + lane * 4) = acc;
}

// ---------------- packed-f32x2 SGEMM, double-buffered BK=16 ----------------
// BM=128, BN=128, BK=16, 256 threads, 8x8 micro-tile as 8x4 f32x2 pairs.
// A stored DUPLICATED transposed in smem: AsD[k][2m]=AsD[k][2m+1]=A[m][k].
// Loop: LDG(next regs) -> compute(cur buf) -> STS(next -> other buf) -> 1 sync.
template<int EPI>
__global__ void __launch_bounds__(256)
k_gemm(const float* __restrict__ B,
       const float* __restrict__ bias, float* __restrict__ Cout,
       const float* __restrict__ thrp) {
    constexpr int K     = (EPI == 0) ? DIN : (EPI == 1) ? HH : MP;
    constexpr int KB    = (EPI == 2) ? MM : K;
    constexpr int Nreal = (EPI == 0) ? HH : (EPI == 1) ? MM : OO;
    constexpr int ldc   = Nreal;
    const float* A = (EPI == 0) ? g_xagg : (EPI == 1) ? g_hagg : g_p;
    float* C = (EPI == 0) ? g_h : Cout;

    constexpr int BK = 16;
    constexpr int ASTR = 260;   // floats per AsD row (1040B = 65*16)
    constexpr int BSTR = 132;   // floats per Bs row  (528B  = 33*16)
    extern __shared__ float sm[];
    float* AsD = sm;                        // [2][16][ASTR]
    float* Bs  = sm + 2 * BK * ASTR;        // [2][16][BSTR]

    int tid = threadIdx.x;
    int tx = tid & 15;    // col group (x8 -> 4 pairs)
    int ty = tid >> 4;    // row group (x8)
    int rowBlk = blockIdx.y * 128;
    int colBlk = blockIdx.x * 128;

    unsigned long long acc[8][4];
#pragma unroll
    for (int i = 0; i < 8; i++)
#pragma unroll
        for (int j = 0; j < 4; j++) acc[i][j] = 0ull;

    // per-thread load coords
    int arow0 = (tid + 0)   >> 2, apart0 = (tid + 0)   & 3;
    int arow1 = (tid + 256) >> 2, apart1 = (tid + 256) & 3;
    int bkk0  = (tid + 0)   >> 5, bn0 = ((tid + 0)   & 31) * 4;
    int bkk1  = (tid + 256) >> 5, bn1 = ((tid + 256) & 31) * 4;
    int agr0 = rowBlk + arow0, agr1 = rowBlk + arow1;
    int bgn0 = colBlk + bn0,   bgn1 = colBlk + bn1;

    float4 aP0, aP1, bP0, bP1;

    auto ldg_tile = [&](int kb) {
        aP0 = make_float4(0.f, 0.f, 0.f, 0.f);
        aP1 = make_float4(0.f, 0.f, 0.f, 0.f);
        if (agr0 < NN) aP0 = *(const float4*)(A + (long)agr0 * K + kb + apart0 * 4);
        if (agr1 < NN) aP1 = *(const float4*)(A + (long)agr1 * K + kb + apart1 * 4);
        bP0 = make_float4(0.f, 0.f, 0.f, 0.f);
        bP1 = make_float4(0.f, 0.f, 0.f, 0.f);
        int gk0 = kb + bkk0, gk1 = kb + bkk1;
        if (gk0 < KB) {
            if (bgn0 + 3 < Nreal) bP0 = *(const float4*)(B + (long)gk0 * Nreal + bgn0);
            else {
                if (bgn0 + 0 < Nreal) bP0.x = B[(long)gk0 * Nreal + bgn0 + 0];
                if (bgn0 + 1 < Nreal) bP0.y = B[(long)gk0 * Nreal + bgn0 + 1];
                if (bgn0 + 2 < Nreal) bP0.z = B[(long)gk0 * Nreal + bgn0 + 2];
            }
        }
        if (gk1 < KB) {
            if (bgn1 + 3 < Nreal) bP1 = *(const float4*)(B + (long)gk1 * Nreal + bgn1);
            else {
                if (bgn1 + 0 < Nreal) bP1.x = B[(long)gk1 * Nreal + bgn1 + 0];
                if (bgn1 + 1 < Nreal) bP1.y = B[(long)gk1 * Nreal + bgn1 + 1];
                if (bgn1 + 2 < Nreal) bP1.z = B[(long)gk1 * Nreal + bgn1 + 2];
            }
        }
    };
    auto sts_tile = [&](int buf) {
        float* Ab = AsD + buf * BK * ASTR;
        float* Bb = Bs  + buf * BK * BSTR;
        *(float2*)&Ab[(apart0 * 4 + 0) * ASTR + 2 * arow0] = make_float2(aP0.x, aP0.x);
        *(float2*)&Ab[(apart0 * 4 + 1) * ASTR + 2 * arow0] = make_float2(aP0.y, aP0.y);
        *(float2*)&Ab[(apart0 * 4 + 2) * ASTR + 2 * arow0] = make_float2(aP0.z, aP0.z);
        *(float2*)&Ab[(apart0 * 4 + 3) * ASTR + 2 * arow0] = make_float2(aP0.w, aP0.w);
        *(float2*)&Ab[(apart1 * 4 + 0) * ASTR + 2 * arow1] = make_float2(aP1.x, aP1.x);
        *(float2*)&Ab[(apart1 * 4 + 1) * ASTR + 2 * arow1] = make_float2(aP1.y, aP1.y);
        *(float2*)&Ab[(apart1 * 4 + 2) * ASTR + 2 * arow1] = make_float2(aP1.z, aP1.z);
        *(float2*)&Ab[(apart1 * 4 + 3) * ASTR + 2 * arow1] = make_float2(aP1.w, aP1.w);
        *(float4*)&Bb[bkk0 * BSTR + bn0] = bP0;
        *(float4*)&Bb[bkk1 * BSTR + bn1] = bP1;
    };
    auto compute_buf = [&](int buf) {
        const float* Ab = AsD + buf * BK * ASTR;
        const float* Bb = Bs  + buf * BK * BSTR;
#pragma unroll
        for (int k = 0; k < BK; k++) {
            ulonglong2 a01 = *(const ulonglong2*)&Ab[k * ASTR + 16 * ty + 0];
            ulonglong2 a23 = *(const ulonglong2*)&Ab[k * ASTR + 16 * ty + 4];
            ulonglong2 a45 = *(const ulonglong2*)&Ab[k * ASTR + 16 * ty + 8];
            ulonglong2 a67 = *(const ulonglong2*)&Ab[k * ASTR + 16 * ty + 12];
            ulonglong2 b01 = *(const ulonglong2*)&Bb[k * BSTR + tx * 8];
            ulonglong2 b23 = *(const ulonglong2*)&Bb[k * BSTR + tx * 8 + 4];
            unsigned long long ap[8] = {a01.x, a01.y, a23.x, a23.y, a45.x, a45.y, a67.x, a67.y};
            unsigned long long bp[4] = {b01.x, b01.y, b23.x, b23.y};
#pragma unroll
            for (int i = 0; i < 8; i++)
#pragma unroll
                for (int j = 0; j < 4; j++) fma2(acc[i][j], ap[i], bp[j]);
        }
    };

    constexpr int NIT = K / BK;
    ldg_tile(0);
    sts_tile(0);
    __syncthreads();
#pragma unroll 2
    for (int it = 0; it < NIT; it++) {
        int cur = it & 1;
        if (it + 1 < NIT) ldg_tile((it + 1) * BK);
        compute_buf(cur);
        if (it + 1 < NIT) {
            sts_tile(cur ^ 1);
            __syncthreads();
        }
    }

    float t = 1.f;
    if (EPI == 1) t = softplus_f(*thrp);
#pragma unroll
    for (int i = 0; i < 8; i++) {
        int gr = rowBlk + ty * 8 + i;
        if (gr >= NN) continue;
#pragma unroll
        for (int j = 0; j < 4; j++) {
            int gn = colBlk + tx * 8 + j * 2;
            float z0, z1;
            unpack2(acc[i][j], z0, z1);
            if (EPI == 0) {
                float2 o;
                o.x = fmaxf(z0 + bias[gn + 0], 0.f);
                o.y = fmaxf(z1 + bias[gn + 1], 0.f);
                *(float2*)(C + (long)gr * ldc + gn) = o;
            } else if (EPI == 1) {
                float2 p = make_float2(0.f, 0.f);
                if (gn < Nreal) {   // pairs never straddle 500
                    float sp0 = softplus_f(z0 + bias[gn + 0]);
                    float sp1 = softplus_f(z1 + bias[gn + 1]);
                    *(float2*)(C + (long)gr * ldc + gn) = make_float2(sp0, sp1);
                    p.x = tanh_f(t * sp0); p.y = tanh_f(t * sp1);
                }
                *(float2*)(g_p + (long)gr * MP + gn) = p;   // zero-pad cols [500,512)
            } else {
                if (gn < Nreal) {   // pairs never straddle 100
                    float2 o;
                    o.x = z0 + bias[gn + 0];
                    o.y = z1 + bias[gn + 1];
                    *(float2*)(C + (long)gr * ldc + gn) = o;
                }
            }
        }
    }
}

// ============================ host launch ============================
extern "C" void kernel_launch(void* const* d_in, const int* in_sizes, int n_in,
                              void* d_out, int out_size) {
    const float* x    = (const float*)d_in[0];
    const int*   ei   = (const int*)d_in[1];     // int32 (JAX x64 disabled)
    const float* W1   = (const float*)d_in[2];
    const float* b1   = (const float*)d_in[3];
    const float* W2   = (const float*)d_in[4];
    const float* b2   = (const float*)d_in[5];
    const float* Wout = (const float*)d_in[6];
    const float* bout = (const float*)d_in[7];
    const float* thr  = (const float*)d_in[8];
    float* out = (float*)d_out;
    float* out_mr = out;                  // [N, M]
    float* out_y  = out + (long)NN * MM;  // [N, O]

    const int SMEM = (2 * 16 * 260 + 2 * 16 * 132) * 4;   // 50176 B
    cudaFuncSetAttribute(k_gemm<0>, cudaFuncAttributeMaxDynamicSharedMemorySize, SMEM);
    cudaFuncSetAttribute(k_gemm<1>, cudaFuncAttributeMaxDynamicSharedMemorySize, SMEM);
    cudaFuncSetAttribute(k_gemm<2>, cudaFuncAttributeMaxDynamicSharedMemorySize, SMEM);

    // graph preprocessing: degrees, dinv, CSR
    k_zero_deg<<<(NN + 255) / 256, 256>>>();
    k_count<<<(EE + 255) / 256, 256>>>(ei);
    k_dinv<<<(NN + 255) / 256, 256>>>();
    k_scan1<<<NBLK, SCAN_B>>>();
    k_scan2<<<1, 128>>>();
    k_scan3<<<(NN + 255) / 256, 256>>>();
    k_fill<<<(EE + 255) / 256, 256>>>(ei);

    int gatherBlocks = (NN * 32 + 255) / 256;   // warp per node
    int rowBlks = (NN + 127) / 128;             // 782

    // layer 1: xagg = self + A_norm x ; h = relu(xagg@W1 + b1)
    k_gather<0><<<gatherBlocks, 256>>>(x, 0);
    k_gemm<0><<<dim3(HH / 128, rowBlks), 256, SMEM>>>(W1, b1, nullptr, nullptr);

    // layer 2: hagg = self + A_norm h (two channel-half passes for L2 residency)
    k_gather<1><<<gatherBlocks, 256>>>(nullptr, 0);
    k_gather<1><<<gatherBlocks, 256>>>(nullptr, 128);
    k_gemm<1><<<dim3(MP / 128, rowBlks), 256, SMEM>>>(W2, b2, out_mr, thr);

    // head: y = p @ Wout + bout  (K padded to 512, B guarded at 500)
    k_gemm<2><<<dim3(1, rowBlks), 256, SMEM>>>(Wout, bout, out_y, nullptr);
}

// round 12
// speedup vs baseline: 1.7498x; 1.7498x over previous
#include <cuda_runtime.h>
#include <cstdint>

// Problem constants: N=100000, E=3200000, DIN=128, H=256, M=500, O=100
#define NN  100000
#define EE  3200000
#define DIN 128
#define HH  256
#define MM  500
#define MP  512
#define OO  100

#define SCAN_B 1024
#define NBLK ((NN + SCAN_B - 1) / SCAN_B)   // 98

// ---- scratch (static device globals; referenced ONLY from device code) ----
__device__ int   g_deg[NN];
__device__ int   g_off[NN];
__device__ int   g_cur[NN];
__device__ int   g_bsum[128];
__device__ int   g_src[EE];
__device__ float g_dinv[NN];
__device__ __align__(16) float g_xagg[NN * DIN];   // 51.2 MB
__device__ __align__(16) float g_h   [NN * HH];    // 102.4 MB
__device__ __align__(16) float g_hagg[NN * HH];    // 102.4 MB
__device__ __align__(16) float g_p   [NN * MP];    // 204.8 MB

// ============================ helpers ============================
__device__ __forceinline__ void fma2(unsigned long long& d, unsigned long long a, unsigned long long b) {
    asm("fma.rn.f32x2 %0, %1, %2, %0;" : "+l"(d) : "l"(a), "l"(b));
}
__device__ __forceinline__ void unpack2(unsigned long long v, float& lo, float& hi) {
    uint32_t l, h;
    asm("mov.b64 {%0, %1}, %2;" : "=r"(l), "=r"(h) : "l"(v));
    lo = __uint_as_float(l); hi = __uint_as_float(h);
}
__device__ __forceinline__ float softplus_f(float z) {
    float e = __expf(-fabsf(z));
    return fmaxf(z, 0.f) + __logf(1.f + e);
}
__device__ __forceinline__ float tanh_f(float x) {
    float e = __expf(-2.f * x);
    return (1.f - e) / (1.f + e);
}

// ============================ graph preprocessing ============================
__global__ void k_zero_deg() {
    int i = blockIdx.x * blockDim.x + threadIdx.x;
    if (i < NN) g_deg[i] = 0;
}
__global__ void k_count(const int* __restrict__ ei) {
    int e = blockIdx.x * blockDim.x + threadIdx.x;
    if (e < EE) { int d = ei[EE + e]; if ((unsigned)d < NN) atomicAdd(&g_deg[d], 1); }
}
__global__ void k_dinv() {
    int i = blockIdx.x * blockDim.x + threadIdx.x;
    if (i < NN) g_dinv[i] = rsqrtf((float)g_deg[i] + 2.0f);
}
__global__ void k_scan1() {
    __shared__ int sm[SCAN_B];
    int t = threadIdx.x, i = blockIdx.x * SCAN_B + t;
    int v = (i < NN) ? g_deg[i] : 0;
    sm[t] = v; __syncthreads();
    for (int s = 1; s < SCAN_B; s <<= 1) {
        int add = (t >= s) ? sm[t - s] : 0;
        __syncthreads(); sm[t] += add; __syncthreads();
    }
    if (i < NN) g_off[i] = sm[t] - v;
    if (t == SCAN_B - 1) g_bsum[blockIdx.x] = sm[t];
}
__global__ void k_scan2() {
    __shared__ int sm[128];
    int t = threadIdx.x;
    int v = (t < NBLK) ? g_bsum[t] : 0;
    sm[t] = v; __syncthreads();
    for (int s = 1; s < 128; s <<= 1) {
        int add = (t >= s) ? sm[t - s] : 0;
        __syncthreads(); sm[t] += add; __syncthreads();
    }
    if (t < NBLK) g_bsum[t] = sm[t] - v;
}
__global__ void k_scan3() {
    int i = blockIdx.x * blockDim.x + threadIdx.x;
    if (i < NN) { int o = g_off[i] + g_bsum[i / SCAN_B]; g_off[i] = o; g_cur[i] = o; }
}
__global__ void k_fill(const int* __restrict__ ei) {
    int e = blockIdx.x * blockDim.x + threadIdx.x;
    if (e < EE) {
        int s = ei[e], d = ei[EE + e];
        if ((unsigned)s < NN && (unsigned)d < NN) g_src[atomicAdd(&g_cur[d], 1)] = s;
    }
}

// ---------------- CSR gather (warp per dst node, 128 channels, 4-edge unroll) ----------------
template<int LAYER>
__global__ void k_gather(const float* __restrict__ Xin, int coff) {
    constexpr int C = (LAYER == 0) ? DIN : HH;
    const float* X = (LAYER == 0) ? Xin : (const float*)g_h;
    float* OUT = (LAYER == 0) ? g_xagg : g_hagg;
    int w = (blockIdx.x * blockDim.x + threadIdx.x) >> 5;
    int lane = threadIdx.x & 31;
    if (w >= NN) return;
    float dv = g_dinv[w];
    const float* Xc = X + coff + lane * 4;
    float4 acc;
    {
        float4 v = *(const float4*)(Xc + (long)w * C);
        float sc = 2.0f * dv * dv;
        acc.x = v.x * sc; acc.y = v.y * sc; acc.z = v.z * sc; acc.w = v.w * sc;
    }
    int off = g_off[w], dg = g_deg[w];
    int j = 0;
    for (; j + 4 <= dg; j += 4) {
        int s0 = g_src[off + j], s1 = g_src[off + j + 1];
        int s2 = g_src[off + j + 2], s3 = g_src[off + j + 3];
        float c0 = g_dinv[s0] * dv, c1 = g_dinv[s1] * dv;
        float c2 = g_dinv[s2] * dv, c3 = g_dinv[s3] * dv;
        float4 v0 = *(const float4*)(Xc + (long)s0 * C);
        float4 v1 = *(const float4*)(Xc + (long)s1 * C);
        float4 v2 = *(const float4*)(Xc + (long)s2 * C);
        float4 v3 = *(const float4*)(Xc + (long)s3 * C);
        acc.x += v0.x * c0 + v1.x * c1 + v2.x * c2 + v3.x * c3;
        acc.y += v0.y * c0 + v1.y * c1 + v2.y * c2 + v3.y * c3;
        acc.z += v0.z * c0 + v1.z * c1 + v2.z * c2 + v3.z * c3;
        acc.w += v0.w * c0 + v1.w * c1 + v2.w * c2 + v3.w * c3;
    }
    for (; j < dg; j++) {
        int s0 = g_src[off + j];
        float c0 = g_dinv[s0] * dv;
        float4 v0 = *(const float4*)(Xc + (long)s0 * C);
        acc.x += v0.x * c0; acc.y += v0.y * c0; acc.z += v0.z * c0; acc.w += v0.w * c0;
    }
    *(float4*)(OUT + coff + (long)w * C + lane * 4) = acc;
}

// ---------------- packed-f32x2 SGEMM, BK=8, register-pipelined loads ----------------
// BM=128, BN=128, BK=8, 256 threads, 8x8 micro-tile as 8x4 f32x2 pairs.
// A stored DUPLICATED transposed in smem: AsD[k][2m]=AsD[k][2m+1]=A[m][k].
// Loop: STS(prefetched regs) -> sync -> LDG(next tile into regs) -> compute -> sync.
template<int EPI>
__global__ void __launch_bounds__(256)
k_gemm(const float* __restrict__ B,
       const float* __restrict__ bias, float* __restrict__ Cout,
       const float* __restrict__ thrp) {
    constexpr int K     = (EPI == 0) ? DIN : (EPI == 1) ? HH : MP;
    constexpr int KB    = (EPI == 2) ? MM : K;
    constexpr int Nreal = (EPI == 0) ? HH : (EPI == 1) ? MM : OO;
    constexpr int ldc   = Nreal;
    const float* A = (EPI == 0) ? g_xagg : (EPI == 1) ? g_hagg : g_p;
    float* C = (EPI == 0) ? g_h : Cout;

    const int BK = 8;
    const int ASTR = 2 * 128 + 4;                 // 260 floats
    __shared__ float AsD[BK][ASTR];
    __shared__ float Bs[BK][128 + 4];
    int tid = threadIdx.x;
    int tx = tid & 15;    // col group (x8 -> 4 pairs)
    int ty = tid >> 4;    // row group (x8)
    int rowBlk = blockIdx.y * 128;
    int colBlk = blockIdx.x * 128;

    unsigned long long acc[8][4];
#pragma unroll
    for (int i = 0; i < 8; i++)
#pragma unroll
        for (int j = 0; j < 4; j++) acc[i][j] = 0ull;

    // per-thread load coords (one float4 each for A and B per tile)
    const int arow = tid >> 1, apart = tid & 1;
    const int bkk = tid >> 5, bn4 = tid & 31;
    const int agr = rowBlk + arow;
    const int bgn = colBlk + bn4 * 4;

    float4 aP, bP;
    auto ldg_tile = [&](int kb) {
        aP = make_float4(0.f, 0.f, 0.f, 0.f);
        if (agr < NN) aP = *(const float4*)(A + (long)agr * K + kb + apart * 4);
        bP = make_float4(0.f, 0.f, 0.f, 0.f);
        int gk = kb + bkk;
        if (gk < KB) {
            if (bgn + 3 < Nreal) bP = *(const float4*)(B + (long)gk * Nreal + bgn);
            else {
                if (bgn + 0 < Nreal) bP.x = B[(long)gk * Nreal + bgn + 0];
                if (bgn + 1 < Nreal) bP.y = B[(long)gk * Nreal + bgn + 1];
                if (bgn + 2 < Nreal) bP.z = B[(long)gk * Nreal + bgn + 2];
            }
        }
    };

    ldg_tile(0);
    const int NIT = K / BK;
    for (int it = 0; it < NIT; it++) {
        // STS prefetched tile
        *(float2*)&AsD[apart * 4 + 0][2 * arow] = make_float2(aP.x, aP.x);
        *(float2*)&AsD[apart * 4 + 1][2 * arow] = make_float2(aP.y, aP.y);
        *(float2*)&AsD[apart * 4 + 2][2 * arow] = make_float2(aP.z, aP.z);
        *(float2*)&AsD[apart * 4 + 3][2 * arow] = make_float2(aP.w, aP.w);
        *(float4*)&Bs[bkk][bn4 * 4] = bP;
        __syncthreads();
        // issue next tile's LDG before compute (latency overlaps FFMA2 block)
        if (it + 1 < NIT) ldg_tile((it + 1) * BK);
#pragma unroll
        for (int k = 0; k < BK; k++) {
            ulonglong2 a01 = *(const ulonglong2*)&AsD[k][16 * ty + 0];
            ulonglong2 a23 = *(const ulonglong2*)&AsD[k][16 * ty + 4];
            ulonglong2 a45 = *(const ulonglong2*)&AsD[k][16 * ty + 8];
            ulonglong2 a67 = *(const ulonglong2*)&AsD[k][16 * ty + 12];
            ulonglong2 b01 = *(const ulonglong2*)&Bs[k][tx * 8];
            ulonglong2 b23 = *(const ulonglong2*)&Bs[k][tx * 8 + 4];
            unsigned long long ap[8] = {a01.x, a01.y, a23.x, a23.y, a45.x, a45.y, a67.x, a67.y};
            unsigned long long bp[4] = {b01.x, b01.y, b23.x, b23.y};
#pragma unroll
            for (int i = 0; i < 8; i++)
#pragma unroll
                for (int j = 0; j < 4; j++) fma2(acc[i][j], ap[i], bp[j]);
        }
        __syncthreads();
    }

    float t = 1.f;
    if (EPI == 1) t = softplus_f(*thrp);
#pragma unroll
    for (int i = 0; i < 8; i++) {
        int gr = rowBlk + ty * 8 + i;
        if (gr >= NN) continue;
#pragma unroll
        for (int j = 0; j < 4; j++) {
            int gn = colBlk + tx * 8 + j * 2;
            float z0, z1;
            unpack2(acc[i][j], z0, z1);
            if (EPI == 0) {
                float2 o;
                o.x = fmaxf(z0 + bias[gn + 0], 0.f);
                o.y = fmaxf(z1 + bias[gn + 1], 0.f);
                *(float2*)(C + (long)gr * ldc + gn) = o;
            } else if (EPI == 1) {
                float2 p = make_float2(0.f, 0.f);
                if (gn < Nreal) {   // pairs never straddle 500
                    float sp0 = softplus_f(z0 + bias[gn + 0]);
                    float sp1 = softplus_f(z1 + bias[gn + 1]);
                    *(float2*)(C + (long)gr * ldc + gn) = make_float2(sp0, sp1);
                    p.x = tanh_f(t * sp0); p.y = tanh_f(t * sp1);
                }
                *(float2*)(g_p + (long)gr * MP + gn) = p;   // zero-pad cols [500,512)
            } else {
                if (gn < Nreal) {   // pairs never straddle 100
                    float2 o;
                    o.x = z0 + bias[gn + 0];
                    o.y = z1 + bias[gn + 1];
                    *(float2*)(C + (long)gr * ldc + gn) = o;
                }
            }
        }
    }
}

// ============================ host launch ============================
extern "C" void kernel_launch(void* const* d_in, const int* in_sizes, int n_in,
                              void* d_out, int out_size) {
    const float* x    = (const float*)d_in[0];
    const int*   ei   = (const int*)d_in[1];     // int32 (JAX x64 disabled)
    const float* W1   = (const float*)d_in[2];
    const float* b1   = (const float*)d_in[3];
    const float* W2   = (const float*)d_in[4];
    const float* b2   = (const float*)d_in[5];
    const float* Wout = (const float*)d_in[6];
    const float* bout = (const float*)d_in[7];
    const float* thr  = (const float*)d_in[8];
    float* out = (float*)d_out;
    float* out_mr = out;                  // [N, M]
    float* out_y  = out + (long)NN * MM;  // [N, O]

    // graph preprocessing: degrees, dinv, CSR
    k_zero_deg<<<(NN + 255) / 256, 256>>>();
    k_count<<<(EE + 255) / 256, 256>>>(ei);
    k_dinv<<<(NN + 255) / 256, 256>>>();
    k_scan1<<<NBLK, SCAN_B>>>();
    k_scan2<<<1, 128>>>();
    k_scan3<<<(NN + 255) / 256, 256>>>();
    k_fill<<<(EE + 255) / 256, 256>>>(ei);

    int gatherBlocks = (NN * 32 + 255) / 256;   // warp per node
    int rowBlks = (NN + 127) / 128;             // 782

    // layer 1: xagg = self + A_norm x ; h = relu(xagg@W1 + b1)
    k_gather<0><<<gatherBlocks, 256>>>(x, 0);
    k_gemm<0><<<dim3(HH / 128, rowBlks), 256>>>(W1, b1, nullptr, nullptr);

    // layer 2: hagg = self + A_norm h (two channel-half passes for L2 residency)
    k_gather<1><<<gatherBlocks, 256>>>(nullptr, 0);
    k_gather<1><<<gatherBlocks, 256>>>(nullptr, 128);
    k_gemm<1><<<dim3(MP / 128, rowBlks), 256>>>(W2, b2, out_mr, thr);

    // head: y = p @ Wout + bout  (K padded to 512, B guarded at 500)
    k_gemm<2><<<dim3(1, rowBlks), 256>>>(Wout, bout, out_y, nullptr);
}

// round 13
// speedup vs baseline: 2.1105x; 1.2061x over previous
#include <cuda_runtime.h>
#include <cstdint>

// Problem constants: N=100000, E=3200000, DIN=128, H=256, M=500, O=100
#define NN  100000
#define EE  3200000
#define DIN 128
#define HH  256
#define MM  500
#define MP  512
#define OO  100

#define SCAN_B 1024
#define NBLK ((NN + SCAN_B - 1) / SCAN_B)   // 98

// ---- scratch (static device globals; referenced ONLY from device code) ----
__device__ int   g_deg[NN];
__device__ int   g_off[NN];
__device__ int   g_cur[NN];
__device__ int   g_bsum[128];
__device__ int   g_src[EE];
__device__ float g_dinv[NN];
__device__ __align__(16) float g_xagg[NN * DIN];   // 51.2 MB
__device__ __align__(16) float g_h   [NN * HH];    // 102.4 MB
__device__ __align__(16) float g_hagg[NN * HH];    // 102.4 MB
__device__ __align__(16) float g_p   [NN * MP];    // 204.8 MB

// ============================ helpers ============================
__device__ __forceinline__ void fma2(unsigned long long& d, unsigned long long a, unsigned long long b) {
    asm("fma.rn.f32x2 %0, %1, %2, %0;" : "+l"(d) : "l"(a), "l"(b));
}
__device__ __forceinline__ unsigned long long pack2(float a) {
    unsigned long long d;
    asm("mov.b64 %0, {%1, %1};" : "=l"(d) : "r"(__float_as_uint(a)));
    return d;
}
__device__ __forceinline__ void unpack2(unsigned long long v, float& lo, float& hi) {
    uint32_t l, h;
    asm("mov.b64 {%0, %1}, %2;" : "=r"(l), "=r"(h) : "l"(v));
    lo = __uint_as_float(l); hi = __uint_as_float(h);
}
__device__ __forceinline__ float softplus_f(float z) {
    float e = __expf(-fabsf(z));
    return fmaxf(z, 0.f) + __logf(1.f + e);
}
__device__ __forceinline__ float tanh_f(float x) {
    float e = __expf(-2.f * x);
    return (1.f - e) / (1.f + e);
}
// B smem swizzle: col' = col + (col>>5)*4  (keeps 8-float groups intact, kills 2-way conflicts)
#define BSWZ(c) ((c) + (((c) >> 5) << 2))

// ============================ graph preprocessing ============================
__global__ void k_zero_deg() {
    int i = blockIdx.x * blockDim.x + threadIdx.x;
    if (i < NN) g_deg[i] = 0;
}
__global__ void k_count(const int* __restrict__ ei) {
    int e = blockIdx.x * blockDim.x + threadIdx.x;
    if (e < EE) { int d = ei[EE + e]; if ((unsigned)d < NN) atomicAdd(&g_deg[d], 1); }
}
__global__ void k_dinv() {
    int i = blockIdx.x * blockDim.x + threadIdx.x;
    if (i < NN) g_dinv[i] = rsqrtf((float)g_deg[i] + 2.0f);
}
__global__ void k_scan1() {
    __shared__ int sm[SCAN_B];
    int t = threadIdx.x, i = blockIdx.x * SCAN_B + t;
    int v = (i < NN) ? g_deg[i] : 0;
    sm[t] = v; __syncthreads();
    for (int s = 1; s < SCAN_B; s <<= 1) {
        int add = (t >= s) ? sm[t - s] : 0;
        __syncthreads(); sm[t] += add; __syncthreads();
    }
    if (i < NN) g_off[i] = sm[t] - v;
    if (t == SCAN_B - 1) g_bsum[blockIdx.x] = sm[t];
}
__global__ void k_scan2() {
    __shared__ int sm[128];
    int t = threadIdx.x;
    int v = (t < NBLK) ? g_bsum[t] : 0;
    sm[t] = v; __syncthreads();
    for (int s = 1; s < 128; s <<= 1) {
        int add = (t >= s) ? sm[t - s] : 0;
        __syncthreads(); sm[t] += add; __syncthreads();
    }
    if (t < NBLK) g_bsum[t] = sm[t] - v;
}
__global__ void k_scan3() {
    int i = blockIdx.x * blockDim.x + threadIdx.x;
    if (i < NN) { int o = g_off[i] + g_bsum[i / SCAN_B]; g_off[i] = o; g_cur[i] = o; }
}
__global__ void k_fill(const int* __restrict__ ei) {
    int e = blockIdx.x * blockDim.x + threadIdx.x;
    if (e < EE) {
        int s = ei[e], d = ei[EE + e];
        if ((unsigned)s < NN && (unsigned)d < NN) g_src[atomicAdd(&g_cur[d], 1)] = s;
    }
}

// ---------------- CSR gather (warp per dst node, 128 channels, 4-edge unroll) ----------------
template<int LAYER>
__global__ void k_gather(const float* __restrict__ Xin, int coff) {
    constexpr int C = (LAYER == 0) ? DIN : HH;
    const float* X = (LAYER == 0) ? Xin : (const float*)g_h;
    float* OUT = (LAYER == 0) ? g_xagg : g_hagg;
    int w = (blockIdx.x * blockDim.x + threadIdx.x) >> 5;
    int lane = threadIdx.x & 31;
    if (w >= NN) return;
    float dv = g_dinv[w];
    const float* Xc = X + coff + lane * 4;
    float4 acc;
    {
        float4 v = *(const float4*)(Xc + (long)w * C);
        float sc = 2.0f * dv * dv;
        acc.x = v.x * sc; acc.y = v.y * sc; acc.z = v.z * sc; acc.w = v.w * sc;
    }
    int off = g_off[w], dg = g_deg[w];
    int j = 0;
    for (; j + 4 <= dg; j += 4) {
        int s0 = g_src[off + j], s1 = g_src[off + j + 1];
        int s2 = g_src[off + j + 2], s3 = g_src[off + j + 3];
        float c0 = g_dinv[s0] * dv, c1 = g_dinv[s1] * dv;
        float c2 = g_dinv[s2] * dv, c3 = g_dinv[s3] * dv;
        float4 v0 = *(const float4*)(Xc + (long)s0 * C);
        float4 v1 = *(const float4*)(Xc + (long)s1 * C);
        float4 v2 = *(const float4*)(Xc + (long)s2 * C);
        float4 v3 = *(const float4*)(Xc + (long)s3 * C);
        acc.x += v0.x * c0 + v1.x * c1 + v2.x * c2 + v3.x * c3;
        acc.y += v0.y * c0 + v1.y * c1 + v2.y * c2 + v3.y * c3;
        acc.z += v0.z * c0 + v1.z * c1 + v2.z * c2 + v3.z * c3;
        acc.w += v0.w * c0 + v1.w * c1 + v2.w * c2 + v3.w * c3;
    }
    for (; j < dg; j++) {
        int s0 = g_src[off + j];
        float c0 = g_dinv[s0] * dv;
        float4 v0 = *(const float4*)(Xc + (long)s0 * C);
        acc.x += v0.x * c0; acc.y += v0.y * c0; acc.z += v0.z * c0; acc.w += v0.w * c0;
    }
    *(float4*)(OUT + coff + (long)w * C + lane * 4) = acc;
}

// ---------------- packed-f32x2 SGEMM, BK=8, register-pipelined, lean smem ----------------
// BM=128, BN=128, BK=8, 256 threads, 8x8 micro-tile as 8x4 f32x2 pairs.
// A stored PLAIN transposed As[k][m] (broadcast LDS + register (a,a) packs).
// B stored with BSWZ swizzle (conflict-free LDS/STS).
// Loop: STS(prefetched regs) -> sync -> LDG(next tile) -> compute -> sync.
template<int EPI>
__global__ void __launch_bounds__(256)
k_gemm(const float* __restrict__ B,
       const float* __restrict__ bias, float* __restrict__ Cout,
       const float* __restrict__ thrp) {
    constexpr int K     = (EPI == 0) ? DIN : (EPI == 1) ? HH : MP;
    constexpr int KB    = (EPI == 2) ? MM : K;
    constexpr int Nreal = (EPI == 0) ? HH : (EPI == 1) ? MM : OO;
    constexpr int ldc   = Nreal;
    const float* A = (EPI == 0) ? g_xagg : (EPI == 1) ? g_hagg : g_p;
    float* C = (EPI == 0) ? g_h : Cout;

    const int BK = 8;
    const int ASTR = 132;   // 128 + 4 pad
    const int BSTR = 140;   // 128 + swizzle span + pad
    __shared__ float As[BK][ASTR];
    __shared__ float Bs[BK][BSTR];
    int tid = threadIdx.x;
    int tx = tid & 15;    // col group (x8 -> 4 pairs)
    int ty = tid >> 4;    // row group (x8)
    int rowBlk = blockIdx.y * 128;
    int colBlk = blockIdx.x * 128;

    unsigned long long acc[8][4];
#pragma unroll
    for (int i = 0; i < 8; i++)
#pragma unroll
        for (int j = 0; j < 4; j++) acc[i][j] = 0ull;

    // per-thread load coords (one float4 each for A and B per tile)
    const int arow = tid >> 1, apart = tid & 1;
    const int bkk = tid >> 5, bn4 = tid & 31;
    const int agr = rowBlk + arow;
    const int bgn = colBlk + bn4 * 4;
    const int bcolp = BSWZ(bn4 * 4);

    float4 aP, bP;
    auto ldg_tile = [&](int kb) {
        aP = make_float4(0.f, 0.f, 0.f, 0.f);
        if (agr < NN) aP = *(const float4*)(A + (long)agr * K + kb + apart * 4);
        bP = make_float4(0.f, 0.f, 0.f, 0.f);
        int gk = kb + bkk;
        if (gk < KB) {
            if (bgn + 3 < Nreal) bP = *(const float4*)(B + (long)gk * Nreal + bgn);
            else {
                if (bgn + 0 < Nreal) bP.x = B[(long)gk * Nreal + bgn + 0];
                if (bgn + 1 < Nreal) bP.y = B[(long)gk * Nreal + bgn + 1];
                if (bgn + 2 < Nreal) bP.z = B[(long)gk * Nreal + bgn + 2];
            }
        }
    };

    ldg_tile(0);
    const int NIT = K / BK;
    for (int it = 0; it < NIT; it++) {
        // STS prefetched tile (A transposed scalar, B swizzled float4)
        As[apart * 4 + 0][arow] = aP.x;
        As[apart * 4 + 1][arow] = aP.y;
        As[apart * 4 + 2][arow] = aP.z;
        As[apart * 4 + 3][arow] = aP.w;
        *(float4*)&Bs[bkk][bcolp] = bP;
        __syncthreads();
        // issue next tile's LDG before compute (latency overlaps FFMA2 block)
        if (it + 1 < NIT) ldg_tile((it + 1) * BK);
#pragma unroll
        for (int k = 0; k < BK; k++) {
            float4 a03 = *(const float4*)&As[k][8 * ty];
            float4 a47 = *(const float4*)&As[k][8 * ty + 4];
            int cb = BSWZ(tx * 8);
            ulonglong2 b01 = *(const ulonglong2*)&Bs[k][cb];
            ulonglong2 b23 = *(const ulonglong2*)&Bs[k][cb + 4];
            unsigned long long ap[8] = {pack2(a03.x), pack2(a03.y), pack2(a03.z), pack2(a03.w),
                                        pack2(a47.x), pack2(a47.y), pack2(a47.z), pack2(a47.w)};
            unsigned long long bp[4] = {b01.x, b01.y, b23.x, b23.y};
#pragma unroll
            for (int i = 0; i < 8; i++)
#pragma unroll
                for (int j = 0; j < 4; j++) fma2(acc[i][j], ap[i], bp[j]);
        }
        __syncthreads();
    }

    float t = 1.f;
    if (EPI == 1) t = softplus_f(*thrp);
#pragma unroll
    for (int i = 0; i < 8; i++) {
        int gr = rowBlk + ty * 8 + i;
        if (gr >= NN) continue;
#pragma unroll
        for (int j = 0; j < 4; j++) {
            int gn = colBlk + tx * 8 + j * 2;
            float z0, z1;
            unpack2(acc[i][j], z0, z1);
            if (EPI == 0) {
                float2 o;
                o.x = fmaxf(z0 + bias[gn + 0], 0.f);
                o.y = fmaxf(z1 + bias[gn + 1], 0.f);
                *(float2*)(C + (long)gr * ldc + gn) = o;
            } else if (EPI == 1) {
                float2 p = make_float2(0.f, 0.f);
                if (gn < Nreal) {   // pairs never straddle 500
                    float sp0 = softplus_f(z0 + bias[gn + 0]);
                    float sp1 = softplus_f(z1 + bias[gn + 1]);
                    *(float2*)(C + (long)gr * ldc + gn) = make_float2(sp0, sp1);
                    p.x = tanh_f(t * sp0); p.y = tanh_f(t * sp1);
                }
                *(float2*)(g_p + (long)gr * MP + gn) = p;   // zero-pad cols [500,512)
            } else {
                if (gn < Nreal) {   // pairs never straddle 100
                    float2 o;
                    o.x = z0 + bias[gn + 0];
                    o.y = z1 + bias[gn + 1];
                    *(float2*)(C + (long)gr * ldc + gn) = o;
                }
            }
        }
    }
}

// ============================ host launch ============================
extern "C" void kernel_launch(void* const* d_in, const int* in_sizes, int n_in,
                              void* d_out, int out_size) {
    const float* x    = (const float*)d_in[0];
    const int*   ei   = (const int*)d_in[1];     // int32 (JAX x64 disabled)
    const float* W1   = (const float*)d_in[2];
    const float* b1   = (const float*)d_in[3];
    const float* W2   = (const float*)d_in[4];
    const float* b2   = (const float*)d_in[5];
    const float* Wout = (const float*)d_in[6];
    const float* bout = (const float*)d_in[7];
    const float* thr  = (const float*)d_in[8];
    float* out = (float*)d_out;
    float* out_mr = out;                  // [N, M]
    float* out_y  = out + (long)NN * MM;  // [N, O]

    // graph preprocessing: degrees, dinv, CSR
    k_zero_deg<<<(NN + 255) / 256, 256>>>();
    k_count<<<(EE + 255) / 256, 256>>>(ei);
    k_dinv<<<(NN + 255) / 256, 256>>>();
    k_scan1<<<NBLK, SCAN_B>>>();
    k_scan2<<<1, 128>>>();
    k_scan3<<<(NN + 255) / 256, 256>>>();
    k_fill<<<(EE + 255) / 256, 256>>>(ei);

    int gatherBlocks = (NN * 32 + 255) / 256;   // warp per node
    int rowBlks = (NN + 127) / 128;             // 782

    // layer 1: xagg = self + A_norm x ; h = relu(xagg@W1 + b1)
    k_gather<0><<<gatherBlocks, 256>>>(x, 0);
    k_gemm<0><<<dim3(HH / 128, rowBlks), 256>>>(W1, b1, nullptr, nullptr);

    // layer 2: hagg = self + A_norm h (two channel-half passes for L2 residency)
    k_gather<1><<<gatherBlocks, 256>>>(nullptr, 0);
    k_gather<1><<<gatherBlocks, 256>>>(nullptr, 128);
    k_gemm<1><<<dim3(MP / 128, rowBlks), 256>>>(W2, b2, out_mr, thr);

    // head: y = p @ Wout + bout  (K padded to 512, B guarded at 500)
    k_gemm<2><<<dim3(1, rowBlks), 256>>>(Wout, bout, out_y, nullptr);
}

// round 16
// speedup vs baseline: 2.1162x; 1.0027x over previous
#include <cuda_runtime.h>
#include <cstdint>

// Problem constants: N=100000, E=3200000, DIN=128, H=256, M=500, O=100
#define NN  100000
#define EE  3200000
#define DIN 128
#define HH  256
#define MM  500
#define MP  512
#define OO  100

#define SCAN_B 1024
#define NBLK ((NN + SCAN_B - 1) / SCAN_B)   // 98

// ---- scratch (static device globals; referenced ONLY from device code) ----
__device__ int   g_deg[NN];
__device__ int   g_off[NN];
__device__ int   g_cur[NN];
__device__ int   g_bsum[128];
__device__ int   g_src[EE];
__device__ float g_dinv[NN];
__device__ __align__(16) float g_xagg[NN * DIN];   // 51.2 MB
__device__ __align__(16) float g_h   [NN * HH];    // 102.4 MB
__device__ __align__(16) float g_hagg[NN * HH];    // 102.4 MB
__device__ __align__(16) float g_p   [NN * MP];    // 204.8 MB

// ============================ helpers ============================
__device__ __forceinline__ void fma2(unsigned long long& d, unsigned long long a, unsigned long long b) {
    asm("fma.rn.f32x2 %0, %1, %2, %0;" : "+l"(d) : "l"(a), "l"(b));
}
__device__ __forceinline__ unsigned long long pack2(float a) {
    unsigned long long d;
    asm("mov.b64 %0, {%1, %1};" : "=l"(d) : "r"(__float_as_uint(a)));
    return d;
}
__device__ __forceinline__ void unpack2(unsigned long long v, float& lo, float& hi) {
    uint32_t l, h;
    asm("mov.b64 {%0, %1}, %2;" : "=r"(l), "=r"(h) : "l"(v));
    lo = __uint_as_float(l); hi = __uint_as_float(h);
}
__device__ __forceinline__ float softplus_f(float z) {
    float e = __expf(-fabsf(z));
    return fmaxf(z, 0.f) + __logf(1.f + e);
}
__device__ __forceinline__ float tanh_f(float x) {
    float e = __expf(-2.f * x);
    return (1.f - e) / (1.f + e);
}
// B smem swizzle: col' = col + (col>>5)*4  (keeps 8-float groups intact, kills 2-way conflicts)
#define BSWZ(c) ((c) + (((c) >> 5) << 2))

// ============================ graph preprocessing ============================
__global__ void k_zero_deg() {
    int i = blockIdx.x * blockDim.x + threadIdx.x;
    if (i < NN) g_deg[i] = 0;
}
__global__ void k_count(const int* __restrict__ ei) {
    int e4 = blockIdx.x * blockDim.x + threadIdx.x;
    if (e4 < EE / 4) {
        int4 d = *(const int4*)(ei + EE + e4 * 4);
        if ((unsigned)d.x < NN) atomicAdd(&g_deg[d.x], 1);
        if ((unsigned)d.y < NN) atomicAdd(&g_deg[d.y], 1);
        if ((unsigned)d.z < NN) atomicAdd(&g_deg[d.z], 1);
        if ((unsigned)d.w < NN) atomicAdd(&g_deg[d.w], 1);
    }
}
__global__ void k_dinv() {
    int i = blockIdx.x * blockDim.x + threadIdx.x;
    if (i < NN) g_dinv[i] = rsqrtf((float)g_deg[i] + 2.0f);
}
__global__ void k_scan1() {
    __shared__ int sm[SCAN_B];
    int t = threadIdx.x, i = blockIdx.x * SCAN_B + t;
    int v = (i < NN) ? g_deg[i] : 0;
    sm[t] = v; __syncthreads();
    for (int s = 1; s < SCAN_B; s <<= 1) {
        int add = (t >= s) ? sm[t - s] : 0;
        __syncthreads(); sm[t] += add; __syncthreads();
    }
    if (i < NN) g_off[i] = sm[t] - v;
    if (t == SCAN_B - 1) g_bsum[blockIdx.x] = sm[t];
}
__global__ void k_scan2() {
    __shared__ int sm[128];
    int t = threadIdx.x;
    int v = (t < NBLK) ? g_bsum[t] : 0;
    sm[t] = v; __syncthreads();
    for (int s = 1; s < 128; s <<= 1) {
        int add = (t >= s) ? sm[t - s] : 0;
        __syncthreads(); sm[t] += add; __syncthreads();
    }
    if (t < NBLK) g_bsum[t] = sm[t] - v;
}
__global__ void k_scan3() {
    int i = blockIdx.x * blockDim.x + threadIdx.x;
    if (i < NN) { int o = g_off[i] + g_bsum[i / SCAN_B]; g_off[i] = o; g_cur[i] = o; }
}
__global__ void k_fill(const int* __restrict__ ei) {
    int e4 = blockIdx.x * blockDim.x + threadIdx.x;
    if (e4 < EE / 4) {
        int4 s = *(const int4*)(ei + e4 * 4);
        int4 d = *(const int4*)(ei + EE + e4 * 4);
        if ((unsigned)s.x < NN && (unsigned)d.x < NN) g_src[atomicAdd(&g_cur[d.x], 1)] = s.x;
        if ((unsigned)s.y < NN && (unsigned)d.y < NN) g_src[atomicAdd(&g_cur[d.y], 1)] = s.y;
        if ((unsigned)s.z < NN && (unsigned)d.z < NN) g_src[atomicAdd(&g_cur[d.z], 1)] = s.z;
        if ((unsigned)s.w < NN && (unsigned)d.w < NN) g_src[atomicAdd(&g_cur[d.w], 1)] = s.w;
    }
}

// ---------------- CSR gather (warp per dst node, 128 channels, 4-edge unroll) ----------------
template<int LAYER>
__global__ void k_gather(const float* __restrict__ Xin, int coff) {
    constexpr int C = (LAYER == 0) ? DIN : HH;
    const float* X = (LAYER == 0) ? Xin : (const float*)g_h;
    float* OUT = (LAYER == 0) ? g_xagg : g_hagg;
    int w = (blockIdx.x * blockDim.x + threadIdx.x) >> 5;
    int lane = threadIdx.x & 31;
    if (w >= NN) return;
    float dv = g_dinv[w];
    const float* Xc = X + coff + lane * 4;
    float4 acc;
    {
        float4 v = *(const float4*)(Xc + (long)w * C);
        float sc = 2.0f * dv * dv;
        acc.x = v.x * sc; acc.y = v.y * sc; acc.z = v.z * sc; acc.w = v.w * sc;
    }
    int off = g_off[w], dg = g_deg[w];
    int j = 0;
    for (; j + 4 <= dg; j += 4) {
        int s0 = g_src[off + j], s1 = g_src[off + j + 1];
        int s2 = g_src[off + j + 2], s3 = g_src[off + j + 3];
        float c0 = g_dinv[s0] * dv, c1 = g_dinv[s1] * dv;
        float c2 = g_dinv[s2] * dv, c3 = g_dinv[s3] * dv;
        float4 v0 = *(const float4*)(Xc + (long)s0 * C);
        float4 v1 = *(const float4*)(Xc + (long)s1 * C);
        float4 v2 = *(const float4*)(Xc + (long)s2 * C);
        float4 v3 = *(const float4*)(Xc + (long)s3 * C);
        acc.x += v0.x * c0 + v1.x * c1 + v2.x * c2 + v3.x * c3;
        acc.y += v0.y * c0 + v1.y * c1 + v2.y * c2 + v3.y * c3;
        acc.z += v0.z * c0 + v1.z * c1 + v2.z * c2 + v3.z * c3;
        acc.w += v0.w * c0 + v1.w * c1 + v2.w * c2 + v3.w * c3;
    }
    for (; j < dg; j++) {
        int s0 = g_src[off + j];
        float c0 = g_dinv[s0] * dv;
        float4 v0 = *(const float4*)(Xc + (long)s0 * C);
        acc.x += v0.x * c0; acc.y += v0.y * c0; acc.z += v0.z * c0; acc.w += v0.w * c0;
    }
    *(float4*)(OUT + coff + (long)w * C + lane * 4) = acc;
}

// ---------------- packed-f32x2 SGEMM, BK=8, double-buffered (1 sync/tile) ----------------
// BM=128, BN=128, BK=8, 256 threads, 8x8 micro-tile as 8x4 f32x2 pairs.
// A stored PLAIN transposed As[buf][k][m] (broadcast LDS + register (a,a) packs).
// B stored with BSWZ swizzle (conflict-free LDS/STS).
// Loop: LDG(next) -> compute(cur buf) -> STS(next -> other buf) -> sync.
template<int EPI>
__global__ void __launch_bounds__(256)
k_gemm(const float* __restrict__ B,
       const float* __restrict__ bias, float* __restrict__ Cout,
       const float* __restrict__ thrp) {
    constexpr int K     = (EPI == 0) ? DIN : (EPI == 1) ? HH : MP;
    constexpr int KB    = (EPI == 2) ? MM : K;
    constexpr int Nreal = (EPI == 0) ? HH : (EPI == 1) ? MM : OO;
    constexpr int ldc   = Nreal;
    const float* A = (EPI == 0) ? g_xagg : (EPI == 1) ? g_hagg : g_p;
    float* C = (EPI == 0) ? g_h : Cout;

    const int BK = 8;
    __shared__ float As[2][BK][132];   // 132 = 128 + 4 pad
    __shared__ float Bs[2][BK][140];   // 140 = 128 + swizzle span + pad
    int tid = threadIdx.x;
    int tx = tid & 15;    // col group (x8 -> 4 pairs)
    int ty = tid >> 4;    // row group (x8)
    int rowBlk = blockIdx.y * 128;
    int colBlk = blockIdx.x * 128;

    unsigned long long acc[8][4];
#pragma unroll
    for (int i = 0; i < 8; i++)
#pragma unroll
        for (int j = 0; j < 4; j++) acc[i][j] = 0ull;

    // per-thread load coords (one float4 each for A and B per tile)
    const int arow = tid >> 1, apart = tid & 1;
    const int bkk = tid >> 5, bn4 = tid & 31;
    const int agr = rowBlk + arow;
    const int bgn = colBlk + bn4 * 4;
    const int bcolp = BSWZ(bn4 * 4);

    float4 aP, bP;
    auto ldg_tile = [&](int kb) {
        aP = make_float4(0.f, 0.f, 0.f, 0.f);
        if (agr < NN) aP = *(const float4*)(A + (long)agr * K + kb + apart * 4);
        bP = make_float4(0.f, 0.f, 0.f, 0.f);
        int gk = kb + bkk;
        if (gk < KB) {
            if (bgn + 3 < Nreal) bP = *(const float4*)(B + (long)gk * Nreal + bgn);
            else {
                if (bgn + 0 < Nreal) bP.x = B[(long)gk * Nreal + bgn + 0];
                if (bgn + 1 < Nreal) bP.y = B[(long)gk * Nreal + bgn + 1];
                if (bgn + 2 < Nreal) bP.z = B[(long)gk * Nreal + bgn + 2];
            }
        }
    };
    auto sts_tile = [&](int b) {
        As[b][apart * 4 + 0][arow] = aP.x;
        As[b][apart * 4 + 1][arow] = aP.y;
        As[b][apart * 4 + 2][arow] = aP.z;
        As[b][apart * 4 + 3][arow] = aP.w;
        *(float4*)&Bs[b][bkk][bcolp] = bP;
    };

    ldg_tile(0);
    sts_tile(0);
    __syncthreads();
    const int NIT = K / BK;
    for (int it = 0; it < NIT; it++) {
        // next tile's LDG issues before compute (latency overlaps FFMA2 block)
        if (it + 1 < NIT) ldg_tile((it + 1) * BK);
        const float (*Ab)[132] = As[it & 1];
        const float (*Bb)[140] = Bs[it & 1];
#pragma unroll
        for (int k = 0; k < BK; k++) {
            float4 a03 = *(const float4*)&Ab[k][8 * ty];
            float4 a47 = *(const float4*)&Ab[k][8 * ty + 4];
            int cb = BSWZ(tx * 8);
            ulonglong2 b01 = *(const ulonglong2*)&Bb[k][cb];
            ulonglong2 b23 = *(const ulonglong2*)&Bb[k][cb + 4];
            unsigned long long ap[8] = {pack2(a03.x), pack2(a03.y), pack2(a03.z), pack2(a03.w),
                                        pack2(a47.x), pack2(a47.y), pack2(a47.z), pack2(a47.w)};
            unsigned long long bp[4] = {b01.x, b01.y, b23.x, b23.y};
#pragma unroll
            for (int i = 0; i < 8; i++)
#pragma unroll
                for (int j = 0; j < 4; j++) fma2(acc[i][j], ap[i], bp[j]);
        }
        // store next tile into the OTHER buffer (safe: nobody reads it this iter)
        if (it + 1 < NIT) {
            sts_tile((it + 1) & 1);
            __syncthreads();
        }
    }

    float t = 1.f;
    if (EPI == 1) t = softplus_f(*thrp);
#pragma unroll
    for (int i = 0; i < 8; i++) {
        int gr = rowBlk + ty * 8 + i;
        if (gr >= NN) continue;
#pragma unroll
        for (int j = 0; j < 4; j++) {
            int gn = colBlk + tx * 8 + j * 2;
            float z0, z1;
            unpack2(acc[i][j], z0, z1);
            if (EPI == 0) {
                float2 o;
                o.x = fmaxf(z0 + bias[gn + 0], 0.f);
                o.y = fmaxf(z1 + bias[gn + 1], 0.f);
                *(float2*)(C + (long)gr * ldc + gn) = o;
            } else if (EPI == 1) {
                float2 p = make_float2(0.f, 0.f);
                if (gn < Nreal) {   // pairs never straddle 500
                    float sp0 = softplus_f(z0 + bias[gn + 0]);
                    float sp1 = softplus_f(z1 + bias[gn + 1]);
                    *(float2*)(C + (long)gr * ldc + gn) = make_float2(sp0, sp1);
                    p.x = tanh_f(t * sp0); p.y = tanh_f(t * sp1);
                }
                *(float2*)(g_p + (long)gr * MP + gn) = p;   // zero-pad cols [500,512)
            } else {
                if (gn < Nreal) {   // pairs never straddle 100
                    float2 o;
                    o.x = z0 + bias[gn + 0];
                    o.y = z1 + bias[gn + 1];
                    *(float2*)(C + (long)gr * ldc + gn) = o;
                }
            }
        }
    }
}

// ============================ host launch ============================
extern "C" void kernel_launch(void* const* d_in, const int* in_sizes, int n_in,
                              void* d_out, int out_size) {
    const float* x    = (const float*)d_in[0];
    const int*   ei   = (const int*)d_in[1];     // int32 (JAX x64 disabled)
    const float* W1   = (const float*)d_in[2];
    const float* b1   = (const float*)d_in[3];
    const float* W2   = (const float*)d_in[4];
    const float* b2   = (const float*)d_in[5];
    const float* Wout = (const float*)d_in[6];
    const float* bout = (const float*)d_in[7];
    const float* thr  = (const float*)d_in[8];
    float* out = (float*)d_out;
    float* out_mr = out;                  // [N, M]
    float* out_y  = out + (long)NN * MM;  // [N, O]

    // graph preprocessing: degrees, dinv, CSR
    k_zero_deg<<<(NN + 255) / 256, 256>>>();
    k_count<<<(EE / 4 + 255) / 256, 256>>>(ei);
    k_dinv<<<(NN + 255) / 256, 256>>>();
    k_scan1<<<NBLK, SCAN_B>>>();
    k_scan2<<<1, 128>>>();
    k_scan3<<<(NN + 255) / 256, 256>>>();
    k_fill<<<(EE / 4 + 255) / 256, 256>>>(ei);

    int gatherBlocks = (NN * 32 + 255) / 256;   // warp per node
    int rowBlks = (NN + 127) / 128;             // 782

    // layer 1: xagg = self + A_norm x ; h = relu(xagg@W1 + b1)
    k_gather<0><<<gatherBlocks, 256>>>(x, 0);
    k_gemm<0><<<dim3(HH / 128, rowBlks), 256>>>(W1, b1, nullptr, nullptr);

    // layer 2: hagg = self + A_norm h (two channel-half passes for L2 residency)
    k_gather<1><<<gatherBlocks, 256>>>(nullptr, 0);
    k_gather<1><<<gatherBlocks, 256>>>(nullptr, 128);
    k_gemm<1><<<dim3(MP / 128, rowBlks), 256>>>(W2, b2, out_mr, thr);

    // head: y = p @ Wout + bout  (K padded to 512, B guarded at 500)
    k_gemm<2><<<dim3(1, rowBlks), 256>>>(Wout, bout, out_y, nullptr);
}

// round 17
// speedup vs baseline: 2.2416x; 1.0593x over previous
#include <cuda_runtime.h>
#include <cuda_fp16.h>
#include <cstdint>

// Problem constants: N=100000, E=3200000, DIN=128, H=256, M=500, O=100
#define NN  100000
#define EE  3200000
#define DIN 128
#define HH  256
#define MM  500
#define MP  512
#define OO  100

#define SCAN_B 1024
#define NBLK ((NN + SCAN_B - 1) / SCAN_B)   // 98

// ---- scratch (static device globals; referenced ONLY from device code) ----
__device__ int   g_deg[NN];
__device__ int   g_off[NN];
__device__ int   g_cur[NN];
__device__ int   g_bsum[128];
__device__ int   g_src[EE];
__device__ float g_dinv[NN];
__device__ __align__(16) __half g_x16[NN * DIN];   // 25.6 MB (fp16 copy of x)
__device__ __align__(16) __half g_h16[NN * HH];    // 51.2 MB (fp16 layer-1 output)
__device__ __align__(16) float g_xagg[NN * DIN];   // 51.2 MB
__device__ __align__(16) float g_hagg[NN * HH];    // 102.4 MB
__device__ __align__(16) float g_p   [NN * MP];    // 204.8 MB

// ============================ helpers ============================
__device__ __forceinline__ void fma2(unsigned long long& d, unsigned long long a, unsigned long long b) {
    asm("fma.rn.f32x2 %0, %1, %2, %0;" : "+l"(d) : "l"(a), "l"(b));
}
__device__ __forceinline__ unsigned long long pack2(float a) {
    unsigned long long d;
    asm("mov.b64 %0, {%1, %1};" : "=l"(d) : "r"(__float_as_uint(a)));
    return d;
}
__device__ __forceinline__ void unpack2(unsigned long long v, float& lo, float& hi) {
    uint32_t l, h;
    asm("mov.b64 {%0, %1}, %2;" : "=r"(l), "=r"(h) : "l"(v));
    lo = __uint_as_float(l); hi = __uint_as_float(h);
}
__device__ __forceinline__ float softplus_f(float z) {
    float e = __expf(-fabsf(z));
    return fmaxf(z, 0.f) + __logf(1.f + e);
}
__device__ __forceinline__ float tanh_f(float x) {
    float e = __expf(-2.f * x);
    return (1.f - e) / (1.f + e);
}
// B smem swizzle: col' = col + (col>>5)*4
#define BSWZ(c) ((c) + (((c) >> 5) << 2))

// ============================ graph preprocessing ============================
__global__ void k_zero_deg() {
    int i = blockIdx.x * blockDim.x + threadIdx.x;
    if (i < NN) g_deg[i] = 0;
}
__global__ void k_count(const int* __restrict__ ei) {
    int e4 = blockIdx.x * blockDim.x + threadIdx.x;
    if (e4 < EE / 4) {
        int4 d = *(const int4*)(ei + EE + e4 * 4);
        if ((unsigned)d.x < NN) atomicAdd(&g_deg[d.x], 1);
        if ((unsigned)d.y < NN) atomicAdd(&g_deg[d.y], 1);
        if ((unsigned)d.z < NN) atomicAdd(&g_deg[d.z], 1);
        if ((unsigned)d.w < NN) atomicAdd(&g_deg[d.w], 1);
    }
}
__global__ void k_dinv() {
    int i = blockIdx.x * blockDim.x + threadIdx.x;
    if (i < NN) g_dinv[i] = rsqrtf((float)g_deg[i] + 2.0f);
}
__global__ void k_scan1() {
    __shared__ int sm[SCAN_B];
    int t = threadIdx.x, i = blockIdx.x * SCAN_B + t;
    int v = (i < NN) ? g_deg[i] : 0;
    sm[t] = v; __syncthreads();
    for (int s = 1; s < SCAN_B; s <<= 1) {
        int add = (t >= s) ? sm[t - s] : 0;
        __syncthreads(); sm[t] += add; __syncthreads();
    }
    if (i < NN) g_off[i] = sm[t] - v;
    if (t == SCAN_B - 1) g_bsum[blockIdx.x] = sm[t];
}
__global__ void k_scan2() {
    __shared__ int sm[128];
    int t = threadIdx.x;
    int v = (t < NBLK) ? g_bsum[t] : 0;
    sm[t] = v; __syncthreads();
    for (int s = 1; s < 128; s <<= 1) {
        int add = (t >= s) ? sm[t - s] : 0;
        __syncthreads(); sm[t] += add; __syncthreads();
    }
    if (t < NBLK) g_bsum[t] = sm[t] - v;
}
__global__ void k_scan3() {
    int i = blockIdx.x * blockDim.x + threadIdx.x;
    if (i < NN) { int o = g_off[i] + g_bsum[i / SCAN_B]; g_off[i] = o; g_cur[i] = o; }
}
__global__ void k_fill(const int* __restrict__ ei) {
    int e4 = blockIdx.x * blockDim.x + threadIdx.x;
    if (e4 < EE / 4) {
        int4 s = *(const int4*)(ei + e4 * 4);
        int4 d = *(const int4*)(ei + EE + e4 * 4);
        if ((unsigned)s.x < NN && (unsigned)d.x < NN) g_src[atomicAdd(&g_cur[d.x], 1)] = s.x;
        if ((unsigned)s.y < NN && (unsigned)d.y < NN) g_src[atomicAdd(&g_cur[d.y], 1)] = s.y;
        if ((unsigned)s.z < NN && (unsigned)d.z < NN) g_src[atomicAdd(&g_cur[d.z], 1)] = s.z;
        if ((unsigned)s.w < NN && (unsigned)d.w < NN) g_src[atomicAdd(&g_cur[d.w], 1)] = s.w;
    }
}

// ---------------- x -> fp16 conversion ----------------
__global__ void k_xhalf(const float* __restrict__ x) {
    int i = blockIdx.x * blockDim.x + threadIdx.x;   // float4 index
    if (i < NN * DIN / 4) {
        float4 v = ((const float4*)x)[i];
        __half2 a = __floats2half2_rn(v.x, v.y);
        __half2 b = __floats2half2_rn(v.z, v.w);
        uint2 o;
        o.x = *(uint32_t*)&a;
        o.y = *(uint32_t*)&b;
        ((uint2*)g_x16)[i] = o;
    }
}

// ---------------- CSR gather (warp per dst node, 128 ch, fp16 inputs, fp32 accum) ----------------
template<int LAYER>
__global__ void k_gather(int coff) {
    constexpr int C = (LAYER == 0) ? DIN : HH;
    const __half* X = (LAYER == 0) ? g_x16 : g_h16;
    float* OUT = (LAYER == 0) ? g_xagg : g_hagg;
    int w = (blockIdx.x * blockDim.x + threadIdx.x) >> 5;
    int lane = threadIdx.x & 31;
    if (w >= NN) return;
    float dv = g_dinv[w];
    const __half* Xc = X + coff + lane * 4;

    auto loadrow = [&](int node) -> float4 {
        uint2 r = *(const uint2*)(Xc + (long)node * C);
        float2 f0 = __half22float2(*(__half2*)&r.x);
        float2 f1 = __half22float2(*(__half2*)&r.y);
        return make_float4(f0.x, f0.y, f1.x, f1.y);
    };

    float4 acc;
    {
        float4 v = loadrow(w);
        float sc = 2.0f * dv * dv;
        acc.x = v.x * sc; acc.y = v.y * sc; acc.z = v.z * sc; acc.w = v.w * sc;
    }
    int off = g_off[w], dg = g_deg[w];
    int j = 0;
    for (; j + 4 <= dg; j += 4) {
        int s0 = g_src[off + j], s1 = g_src[off + j + 1];
        int s2 = g_src[off + j + 2], s3 = g_src[off + j + 3];
        float c0 = g_dinv[s0] * dv, c1 = g_dinv[s1] * dv;
        float c2 = g_dinv[s2] * dv, c3 = g_dinv[s3] * dv;
        float4 v0 = loadrow(s0);
        float4 v1 = loadrow(s1);
        float4 v2 = loadrow(s2);
        float4 v3 = loadrow(s3);
        acc.x += v0.x * c0 + v1.x * c1 + v2.x * c2 + v3.x * c3;
        acc.y += v0.y * c0 + v1.y * c1 + v2.y * c2 + v3.y * c3;
        acc.z += v0.z * c0 + v1.z * c1 + v2.z * c2 + v3.z * c3;
        acc.w += v0.w * c0 + v1.w * c1 + v2.w * c2 + v3.w * c3;
    }
    for (; j < dg; j++) {
        int s0 = g_src[off + j];
        float c0 = g_dinv[s0] * dv;
        float4 v0 = loadrow(s0);
        acc.x += v0.x * c0; acc.y += v0.y * c0; acc.z += v0.z * c0; acc.w += v0.w * c0;
    }
    *(float4*)(OUT + coff + (long)w * C + lane * 4) = acc;
}

// ---------------- packed-f32x2 SGEMM, BK=8, double-buffered (1 sync/tile) ----------------
// EPI 0: A=g_xagg K=128 -> g_h16 (fp16), ReLU.
// EPI 1: A=g_hagg K=256 -> out_mr (softplus) + g_p = tanh(t*softplus) (ld MP, 0-pad).
// EPI 2: A=g_p K=512 (KB=500 guard on B) -> out_y.
template<int EPI>
__global__ void __launch_bounds__(256)
k_gemm(const float* __restrict__ B,
       const float* __restrict__ bias, float* __restrict__ Cout,
       const float* __restrict__ thrp) {
    constexpr int K     = (EPI == 0) ? DIN : (EPI == 1) ? HH : MP;
    constexpr int KB    = (EPI == 2) ? MM : K;
    constexpr int Nreal = (EPI == 0) ? HH : (EPI == 1) ? MM : OO;
    constexpr int ldc   = Nreal;
    const float* A = (EPI == 0) ? g_xagg : (EPI == 1) ? g_hagg : g_p;

    const int BK = 8;
    __shared__ float As[2][BK][132];   // 132 = 128 + 4 pad
    __shared__ float Bs[2][BK][140];   // 140 = 128 + swizzle span + pad
    int tid = threadIdx.x;
    int tx = tid & 15;    // col group (x8 -> 4 pairs)
    int ty = tid >> 4;    // row group (x8)
    int rowBlk = blockIdx.y * 128;
    int colBlk = blockIdx.x * 128;

    unsigned long long acc[8][4];
#pragma unroll
    for (int i = 0; i < 8; i++)
#pragma unroll
        for (int j = 0; j < 4; j++) acc[i][j] = 0ull;

    const int arow = tid >> 1, apart = tid & 1;
    const int bkk = tid >> 5, bn4 = tid & 31;
    const int agr = rowBlk + arow;
    const int bgn = colBlk + bn4 * 4;
    const int bcolp = BSWZ(bn4 * 4);

    float4 aP, bP;
    auto ldg_tile = [&](int kb) {
        aP = make_float4(0.f, 0.f, 0.f, 0.f);
        if (agr < NN) aP = *(const float4*)(A + (long)agr * K + kb + apart * 4);
        bP = make_float4(0.f, 0.f, 0.f, 0.f);
        int gk = kb + bkk;
        if (gk < KB) {
            if (bgn + 3 < Nreal) bP = *(const float4*)(B + (long)gk * Nreal + bgn);
            else {
                if (bgn + 0 < Nreal) bP.x = B[(long)gk * Nreal + bgn + 0];
                if (bgn + 1 < Nreal) bP.y = B[(long)gk * Nreal + bgn + 1];
                if (bgn + 2 < Nreal) bP.z = B[(long)gk * Nreal + bgn + 2];
            }
        }
    };
    auto sts_tile = [&](int b) {
        As[b][apart * 4 + 0][arow] = aP.x;
        As[b][apart * 4 + 1][arow] = aP.y;
        As[b][apart * 4 + 2][arow] = aP.z;
        As[b][apart * 4 + 3][arow] = aP.w;
        *(float4*)&Bs[b][bkk][bcolp] = bP;
    };

    ldg_tile(0);
    sts_tile(0);
    __syncthreads();
    const int NIT = K / BK;
    for (int it = 0; it < NIT; it++) {
        if (it + 1 < NIT) ldg_tile((it + 1) * BK);
        const float (*Ab)[132] = As[it & 1];
        const float (*Bb)[140] = Bs[it & 1];
#pragma unroll
        for (int k = 0; k < BK; k++) {
            float4 a03 = *(const float4*)&Ab[k][8 * ty];
            float4 a47 = *(const float4*)&Ab[k][8 * ty + 4];
            int cb = BSWZ(tx * 8);
            ulonglong2 b01 = *(const ulonglong2*)&Bb[k][cb];
            ulonglong2 b23 = *(const ulonglong2*)&Bb[k][cb + 4];
            unsigned long long ap[8] = {pack2(a03.x), pack2(a03.y), pack2(a03.z), pack2(a03.w),
                                        pack2(a47.x), pack2(a47.y), pack2(a47.z), pack2(a47.w)};
            unsigned long long bp[4] = {b01.x, b01.y, b23.x, b23.y};
#pragma unroll
            for (int i = 0; i < 8; i++)
#pragma unroll
                for (int j = 0; j < 4; j++) fma2(acc[i][j], ap[i], bp[j]);
        }
        if (it + 1 < NIT) {
            sts_tile((it + 1) & 1);
            __syncthreads();
        }
    }

    float t = 1.f;
    if (EPI == 1) t = softplus_f(*thrp);
#pragma unroll
    for (int i = 0; i < 8; i++) {
        int gr = rowBlk + ty * 8 + i;
        if (gr >= NN) continue;
#pragma unroll
        for (int j = 0; j < 4; j++) {
            int gn = colBlk + tx * 8 + j * 2;
            float z0, z1;
            unpack2(acc[i][j], z0, z1);
            if (EPI == 0) {
                float r0 = fmaxf(z0 + bias[gn + 0], 0.f);
                float r1 = fmaxf(z1 + bias[gn + 1], 0.f);
                __half2 hh = __floats2half2_rn(r0, r1);
                *(__half2*)(g_h16 + (size_t)gr * HH + gn) = hh;
            } else if (EPI == 1) {
                float2 p = make_float2(0.f, 0.f);
                if (gn < Nreal) {   // pairs never straddle 500
                    float sp0 = softplus_f(z0 + bias[gn + 0]);
                    float sp1 = softplus_f(z1 + bias[gn + 1]);
                    *(float2*)(Cout + (long)gr * ldc + gn) = make_float2(sp0, sp1);
                    p.x = tanh_f(t * sp0); p.y = tanh_f(t * sp1);
                }
                *(float2*)(g_p + (long)gr * MP + gn) = p;   // zero-pad cols [500,512)
            } else {
                if (gn < Nreal) {   // pairs never straddle 100
                    float2 o;
                    o.x = z0 + bias[gn + 0];
                    o.y = z1 + bias[gn + 1];
                    *(float2*)(Cout + (long)gr * ldc + gn) = o;
                }
            }
        }
    }
}

// ============================ host launch ============================
extern "C" void kernel_launch(void* const* d_in, const int* in_sizes, int n_in,
                              void* d_out, int out_size) {
    const float* x    = (const float*)d_in[0];
    const int*   ei   = (const int*)d_in[1];     // int32 (JAX x64 disabled)
    const float* W1   = (const float*)d_in[2];
    const float* b1   = (const float*)d_in[3];
    const float* W2   = (const float*)d_in[4];
    const float* b2   = (const float*)d_in[5];
    const float* Wout = (const float*)d_in[6];
    const float* bout = (const float*)d_in[7];
    const float* thr  = (const float*)d_in[8];
    float* out = (float*)d_out;
    float* out_mr = out;                  // [N, M]
    float* out_y  = out + (long)NN * MM;  // [N, O]

    // graph preprocessing: degrees, dinv, CSR (+ fp16 x copy)
    k_zero_deg<<<(NN + 255) / 256, 256>>>();
    k_count<<<(EE / 4 + 255) / 256, 256>>>(ei);
    k_xhalf<<<(NN * DIN / 4 + 255) / 256, 256>>>(x);
    k_dinv<<<(NN + 255) / 256, 256>>>();
    k_scan1<<<NBLK, SCAN_B>>>();
    k_scan2<<<1, 128>>>();
    k_scan3<<<(NN + 255) / 256, 256>>>();
    k_fill<<<(EE / 4 + 255) / 256, 256>>>(ei);

    int gatherBlocks = (NN * 32 + 255) / 256;   // warp per node
    int rowBlks = (NN + 127) / 128;             // 782

    // layer 1: xagg = self + A_norm x ; h16 = relu(xagg@W1 + b1)
    k_gather<0><<<gatherBlocks, 256>>>(0);
    k_gemm<0><<<dim3(HH / 128, rowBlks), 256>>>(W1, b1, nullptr, nullptr);

    // layer 2: hagg = self + A_norm h (two channel-half passes for L2 residency)
    k_gather<1><<<gatherBlocks, 256>>>(0);
    k_gather<1><<<gatherBlocks, 256>>>(128);
    k_gemm<1><<<dim3(MP / 128, rowBlks), 256>>>(W2, b2, out_mr, thr);

    // head: y = p @ Wout + bout  (K padded to 512, B guarded at 500)
    k_gemm<2><<<dim3(1, rowBlks), 256>>>(Wout, bout, out_y, nullptr);
}